// round 2
// baseline (speedup 1.0000x reference)
#include <cuda_runtime.h>
#include <math.h>

// Problem constants (B=4, T=2048)
#define NTOK   8192      // B*T
#define DM     2048      // d_model
#define DE     1024      // d_expert (== d_ff of routed experts)
#define NE     8         // experts
#define TOPK   2
#define CAP    2560      // ceil(NTOK*TOPK/NE * 1.25)
#define NR     (NTOK*TOPK)   // 16384 routes
#define NCHUNK 64
#define CHUNK  256           // NCHUNK*CHUNK == NR

typedef unsigned long long ull;

// ---------------- scratch (device globals; allocation-free) ----------------
__device__ float g_s[NTOK * NE];            // softmax probs (for importance)
__device__ float g_gsh[NTOK];               // sigmoid gate for shared expert
__device__ int   g_tope[NR];                // top-k expert per route
__device__ float g_topg[NR];                // top-k gate value per route
__device__ int   g_partial[NCHUNK * NE];
__device__ int   g_choff[NCHUNK * NE];
__device__ int   g_counts[NE];              // pre-capacity counts (for load stat)
__device__ int   g_ckept[NE];               // min(count, CAP)
__device__ int   g_etok[NE * CAP];          // token index per (expert, slot)
__device__ int   g_rslot[NR];               // route -> global slot (e*CAP+pos) or -1
__device__ float g_h[NE * CAP * DE];        // 80 MB; expert hidden, reused for shared hidden
__device__ float g_slots[NE * CAP * DM];    // 160 MB; expert outputs per slot

// ---------------- packed fp32x2 FMA (Blackwell FFMA2) ----------------
__device__ __forceinline__ void ffma2(ull& d, ull a, ull b) {
    asm("fma.rn.f32x2 %0, %1, %2, %0;" : "+l"(d) : "l"(a), "l"(b));
}
__device__ __forceinline__ float lo32(ull v) { return __uint_as_float((unsigned)(v & 0xffffffffull)); }
__device__ __forceinline__ float hi32(ull v) { return __uint_as_float((unsigned)(v >> 32)); }

// ---------------- router: logits, softmax, top-2, shared gate ----------------
__global__ void router_kernel(const float* __restrict__ x,
                              const float* __restrict__ rw,
                              const float* __restrict__ gw) {
    int n = blockIdx.x;
    const float* xr = x + (size_t)n * DM;
    int t = threadIdx.x;            // 256 threads = 8 warps
    int w = t >> 5, lane = t & 31;
    __shared__ float sm[9];

    const float* wr = rw + w * DM;
    float acc = 0.f;
    for (int k = lane; k < DM; k += 32) acc += xr[k] * wr[k];
    #pragma unroll
    for (int o = 16; o; o >>= 1) acc += __shfl_xor_sync(0xffffffffu, acc, o);
    if (lane == 0) sm[w] = acc;

    if (w == 0) {
        float g = 0.f;
        for (int k = lane; k < DM; k += 32) g += xr[k] * gw[k];
        #pragma unroll
        for (int o = 16; o; o >>= 1) g += __shfl_xor_sync(0xffffffffu, g, o);
        if (lane == 0) sm[8] = g;
    }
    __syncthreads();

    if (t == 0) {
        float l[NE];
        float mx = -1e30f;
        #pragma unroll
        for (int e = 0; e < NE; e++) { l[e] = sm[e]; mx = fmaxf(mx, l[e]); }
        float den = 0.f;
        #pragma unroll
        for (int e = 0; e < NE; e++) { l[e] = expf(l[e] - mx); den += l[e]; }
        float inv = 1.f / den;
        int b0 = 0; float v0 = -1.f;
        #pragma unroll
        for (int e = 0; e < NE; e++) {
            float p = l[e] * inv;
            g_s[n * NE + e] = p;
            if (p > v0) { v0 = p; b0 = e; }
        }
        int b1 = 0; float v1 = -1.f;
        #pragma unroll
        for (int e = 0; e < NE; e++) {
            if (e == b0) continue;
            float p = l[e] * inv;
            if (p > v1) { v1 = p; b1 = e; }
        }
        g_tope[2 * n]     = b0;  g_topg[2 * n]     = v0;
        g_tope[2 * n + 1] = b1;  g_topg[2 * n + 1] = v1;
        g_gsh[n] = 1.f / (1.f + expf(-sm[8]));
    }
}

// ---------------- dispatch bookkeeping (stable, deterministic) ----------------
__global__ void hist_kernel() {
    __shared__ int h[NE];
    int t = threadIdx.x;
    if (t < NE) h[t] = 0;
    __syncthreads();
    atomicAdd(&h[g_tope[blockIdx.x * CHUNK + t]], 1);
    __syncthreads();
    if (t < NE) g_partial[blockIdx.x * NE + t] = h[t];
}

__global__ void scan_kernel() {
    int e = threadIdx.x;
    if (e >= NE) return;
    int run = 0;
    for (int b = 0; b < NCHUNK; b++) { g_choff[b * NE + e] = run; run += g_partial[b * NE + e]; }
    g_counts[e] = run;
    g_ckept[e] = run < CAP ? run : CAP;
}

// Parallel within-chunk stable position assignment.
__global__ void build_kernel() {
    __shared__ int se[CHUNK];
    const int b = blockIdx.x, i = threadIdx.x;
    const int r = b * CHUNK + i;
    const int e = g_tope[r];
    se[i] = e;
    __syncthreads();
    int pos = g_choff[b * NE + e];
    for (int j = 0; j < i; j++) pos += (se[j] == e);
    if (pos < CAP) { g_etok[e * CAP + pos] = r >> 1; g_rslot[r] = e * CAP + pos; }
    else           { g_rslot[r] = -1; }
}

// ---------------- tiled SGEMM (FFMA2) with gather + fused epilogues ----------------
// Out[m,f] = sum_k A[m,k] * W[k,f]        (WT=false; W row-major [K,F])
// Out[m,f] = sum_k A[m,k] * W[f,k]        (WT=true;  W row-major [F,K])
// EPI: 0 = none, 1 = exact GELU, 2 = scale by gsh[m] (write, not add)
__device__ __forceinline__ float gelu_exact(float v) {
    return 0.5f * v * (1.0f + erff(v * 0.70710678118654752f));
}

template<bool WT, int EPI>
__global__ void __launch_bounds__(256)
sgemm_kernel(const float* __restrict__ X, const int* __restrict__ gidx,
             int ldx, int strideXrow,
             const float* __restrict__ W, long long strideW,
             float* __restrict__ Out, long long strideOut, int ldo,
             const int* __restrict__ Mcnts, int Mfixed,
             int F, int Kd, const float* __restrict__ gsh) {
    const int z = blockIdx.z;
    const int M = Mcnts ? Mcnts[z] : Mfixed;
    const int m0 = blockIdx.y * 128;
    if (m0 >= M) return;
    const int n0 = blockIdx.x * 64;

    const float* Wz = W + (size_t)z * strideW;
    float* Oz = Out + (size_t)z * strideOut;
    const int* idxz = gidx ? gidx + z * CAP : nullptr;
    const long long rowbase = (long long)z * strideXrow;

    __shared__ __align__(16) float As[16 * 128];   // transposed: As[k][m]
    __shared__ __align__(16) float Bs[16 * 128];   // duplicated: Bs[k][2f]=Bs[k][2f+1]=b[f]

    const int tid = threadIdx.x;
    const int ty = tid >> 4, tx = tid & 15;

    // 16 packed accumulators: acc[p][j] holds rows (ty*8+2p, ty*8+2p+1), col tx*4+j
    ull acc[4][4];
    #pragma unroll
    for (int p = 0; p < 4; p++)
        #pragma unroll
        for (int j = 0; j < 4; j++) acc[p][j] = 0ull;

    // A-tile load plan: 512 float4 per tile, 2 per thread
    const int q0 = tid * 2;
    const int ar0 = q0 >> 2,       ak0 = (q0 & 3) * 4;
    const int ar1 = (q0 + 1) >> 2, ak1 = ((q0 + 1) & 3) * 4;
    const bool va0 = (m0 + ar0) < M;
    const bool va1 = (m0 + ar1) < M;
    const long long gr0 = va0 ? (idxz ? (long long)idxz[m0 + ar0] : rowbase + m0 + ar0) : 0;
    const long long gr1 = va1 ? (idxz ? (long long)idxz[m0 + ar1] : rowbase + m0 + ar1) : 0;
    const float* pa0 = X + gr0 * ldx;
    const float* pa1 = X + gr1 * ldx;

    for (int k0 = 0; k0 < Kd; k0 += 16) {
        float4 a = va0 ? *(const float4*)(pa0 + k0 + ak0) : make_float4(0, 0, 0, 0);
        As[(ak0 + 0) * 128 + ar0] = a.x; As[(ak0 + 1) * 128 + ar0] = a.y;
        As[(ak0 + 2) * 128 + ar0] = a.z; As[(ak0 + 3) * 128 + ar0] = a.w;
        a = va1 ? *(const float4*)(pa1 + k0 + ak1) : make_float4(0, 0, 0, 0);
        As[(ak1 + 0) * 128 + ar1] = a.x; As[(ak1 + 1) * 128 + ar1] = a.y;
        As[(ak1 + 2) * 128 + ar1] = a.z; As[(ak1 + 3) * 128 + ar1] = a.w;

        if (!WT) {
            const int bk = tid >> 4, bf = (tid & 15) * 4;
            float4 b = *(const float4*)(Wz + (size_t)(k0 + bk) * F + n0 + bf);
            float4 d0 = make_float4(b.x, b.x, b.y, b.y);
            float4 d1 = make_float4(b.z, b.z, b.w, b.w);
            *(float4*)&Bs[bk * 128 + 2 * bf]     = d0;
            *(float4*)&Bs[bk * 128 + 2 * bf + 4] = d1;
        } else {
            const int bf = tid >> 2, bk = (tid & 3) * 4;
            float4 b = *(const float4*)(Wz + (size_t)(n0 + bf) * Kd + k0 + bk);
            *(float2*)&Bs[(bk + 0) * 128 + 2 * bf] = make_float2(b.x, b.x);
            *(float2*)&Bs[(bk + 1) * 128 + 2 * bf] = make_float2(b.y, b.y);
            *(float2*)&Bs[(bk + 2) * 128 + 2 * bf] = make_float2(b.z, b.z);
            *(float2*)&Bs[(bk + 3) * 128 + 2 * bf] = make_float2(b.w, b.w);
        }
        __syncthreads();

        #pragma unroll
        for (int kk = 0; kk < 16; kk++) {
            const ull* ap = (const ull*)&As[kk * 128 + ty * 8];   // 4 row-pairs
            const ull* bp = (const ull*)&Bs[kk * 128 + tx * 8];   // 4 dup'd cols
            ull av[4], bv[4];
            #pragma unroll
            for (int p = 0; p < 4; p++) av[p] = ap[p];
            #pragma unroll
            for (int j = 0; j < 4; j++) bv[j] = bp[j];
            #pragma unroll
            for (int p = 0; p < 4; p++)
                #pragma unroll
                for (int j = 0; j < 4; j++)
                    ffma2(acc[p][j], av[p], bv[j]);
        }
        __syncthreads();
    }

    #pragma unroll
    for (int p = 0; p < 4; p++) {
        const int mA = m0 + ty * 8 + 2 * p;
        float4 v0 = make_float4(lo32(acc[p][0]), lo32(acc[p][1]), lo32(acc[p][2]), lo32(acc[p][3]));
        float4 v1 = make_float4(hi32(acc[p][0]), hi32(acc[p][1]), hi32(acc[p][2]), hi32(acc[p][3]));
        if (EPI == 1) {
            v0.x = gelu_exact(v0.x); v0.y = gelu_exact(v0.y);
            v0.z = gelu_exact(v0.z); v0.w = gelu_exact(v0.w);
            v1.x = gelu_exact(v1.x); v1.y = gelu_exact(v1.y);
            v1.z = gelu_exact(v1.z); v1.w = gelu_exact(v1.w);
        } else if (EPI == 2) {
            const float ga = gsh[mA], gb = gsh[mA + 1];
            v0.x *= ga; v0.y *= ga; v0.z *= ga; v0.w *= ga;
            v1.x *= gb; v1.y *= gb; v1.z *= gb; v1.w *= gb;
        }
        *(float4*)(Oz + (size_t)mA * ldo + n0 + tx * 4)       = v0;
        *(float4*)(Oz + (size_t)(mA + 1) * ldo + n0 + tx * 4) = v1;
    }
}

// ---------------- combine: out += sum of kept routed contributions ----------------
__global__ void combine_kernel(float* __restrict__ out) {
    const int n = blockIdx.x;
    const int s0 = g_rslot[2 * n], s1 = g_rslot[2 * n + 1];
    const float g0 = g_topg[2 * n], g1 = g_topg[2 * n + 1];
    float* o = out + (size_t)n * DM;
    for (int d = threadIdx.x * 4; d < DM; d += 1024) {
        float4 v = *(float4*)&o[d];
        if (s0 >= 0) {
            float4 a = *(const float4*)&g_slots[(size_t)s0 * DM + d];
            v.x += g0 * a.x; v.y += g0 * a.y; v.z += g0 * a.z; v.w += g0 * a.w;
        }
        if (s1 >= 0) {
            float4 a = *(const float4*)&g_slots[(size_t)s1 * DM + d];
            v.x += g1 * a.x; v.y += g1 * a.y; v.z += g1 * a.z; v.w += g1 * a.w;
        }
        *(float4*)&o[d] = v;
    }
}

// ---------------- stats ----------------
__global__ void importance_kernel(float* __restrict__ out) {
    const int e = blockIdx.x;
    const int t = threadIdx.x;
    float s = 0.f;
    for (int i = t; i < NTOK; i += 256) s += g_s[i * NE + e];
    __shared__ float red[256];
    red[t] = s; __syncthreads();
    for (int o = 128; o; o >>= 1) { if (t < o) red[t] += red[t + o]; __syncthreads(); }
    if (t == 0) out[(size_t)NTOK * DM + e] = red[0] / (float)NTOK;
}

__global__ void load_kernel(float* __restrict__ out) {
    const int e = threadIdx.x;
    if (e < NE) out[(size_t)NTOK * DM + NE + e] = (float)g_counts[e] / (float)NR;
}

// ---------------- launch ----------------
extern "C" void kernel_launch(void* const* d_in, const int* in_sizes, int n_in,
                              void* d_out, int out_size) {
    const float* x   = (const float*)d_in[0];   // [B,T,DM]
    const float* rw  = (const float*)d_in[1];   // [E,DM]
    const float* gw  = (const float*)d_in[2];   // [1,DM]
    const float* w1  = (const float*)d_in[3];   // [E,DM,DE]
    const float* w2  = (const float*)d_in[4];   // [E,DE,DM]
    const float* sw1 = (const float*)d_in[5];   // [DFF,DM] (NT)
    const float* sw2 = (const float*)d_in[6];   // [DM,DFF] (NT)
    float* out = (float*)d_out;

    void *p_etok, *p_ckept, *p_h, *p_slots, *p_gsh;
    cudaGetSymbolAddress(&p_etok,  g_etok);
    cudaGetSymbolAddress(&p_ckept, g_ckept);
    cudaGetSymbolAddress(&p_h,     g_h);
    cudaGetSymbolAddress(&p_slots, g_slots);
    cudaGetSymbolAddress(&p_gsh,   g_gsh);

    router_kernel<<<NTOK, 256>>>(x, rw, gw);
    hist_kernel<<<NCHUNK, CHUNK>>>();
    scan_kernel<<<1, 32>>>();
    build_kernel<<<NCHUNK, CHUNK>>>();

    // expert pass 1: h = gelu(x[tok] @ w1[e])   [M<=CAP, DE], K=DM, NN
    dim3 gp1(DE / 64, CAP / 128, NE);
    sgemm_kernel<false, 1><<<gp1, 256>>>(x, (const int*)p_etok, DM, 0,
                                         w1, (long long)DM * DE,
                                         (float*)p_h, (long long)CAP * DE, DE,
                                         (const int*)p_ckept, 0, DE, DM, nullptr);
    // expert pass 2: slots = h @ w2[e]          [M<=CAP, DM], K=DE, NN
    dim3 gp2(DM / 64, CAP / 128, NE);
    sgemm_kernel<false, 0><<<gp2, 256>>>((const float*)p_h, nullptr, DE, CAP,
                                         w2, (long long)DE * DM,
                                         (float*)p_slots, (long long)CAP * DM, DM,
                                         (const int*)p_ckept, 0, DM, DE, nullptr);
    // shared pass 1: h = gelu(x @ sw1^T)        [NTOK, DE], K=DM, NT
    dim3 gs1(DE / 64, NTOK / 128, 1);
    sgemm_kernel<true, 1><<<gs1, 256>>>(x, nullptr, DM, 0,
                                        sw1, 0,
                                        (float*)p_h, 0, DE,
                                        nullptr, NTOK, DE, DM, nullptr);
    // shared pass 2: out = gsh * (h @ sw2^T)    [NTOK, DM], K=DE, NT
    dim3 gs2(DM / 64, NTOK / 128, 1);
    sgemm_kernel<true, 2><<<gs2, 256>>>((const float*)p_h, nullptr, DE, 0,
                                        sw2, 0,
                                        out, 0, DM,
                                        nullptr, NTOK, DM, DE, (const float*)p_gsh);

    combine_kernel<<<NTOK, 256>>>(out);

    if (out_size >= NTOK * DM + 2 * NE) {
        importance_kernel<<<NE, 256>>>(out);
        load_kernel<<<1, NE>>>(out);
    }
}